// round 16
// baseline (speedup 1.0000x reference)
#include <cuda_runtime.h>
#include <cuda_fp16.h>
#include <cstdint>

#define NS   16384
#define DD   128
#define KK   10000
#define KT   128
#define NT2  79             // k-tiles; 79*128 = 10112
#define KPAD (NT2 * KT)
#define TM   128
#define GRID 148
#define GRID2 296           // vq_main: 2 CTAs/SM
#define NSLOT 4             // max CTAs covering one sample tile

// ---- vq_main smem layout (hi split only) ----
#define OFF_A  0            // 32768: x-tile hi split, swizzled fp16
#define OFF_B  32768        // 2 x 32768 buffers
#define BUFB   32768
#define OFF_H  98304        // 2 x 512
#define SMEM_TOTAL (OFF_H + 1024)

// ---- fallback2 smem layout (hi+mid splits) ----
#define F2_OFF_A 0          // 2 x 32768 (hi, mid)
#define F2_OFF_B 65536      // 65536 (hi|mid), single buffer
#define F2_OFF_H 131072     // 512
#define F2_OFF_S 131584     // 128 ints (sample ids)
#define F2_SMEM  (F2_OFF_S + 512)

__device__ uint4 g_B4[(size_t)NT2 * 4096];               // hi+mid swizzled B tiles
__device__ __align__(16) float g_cmT[(size_t)KPAD * DD]; // transposed means [k][d]
__device__ __align__(16) float g_h[KPAD];                // 0.5*||m||^2 (pad -> -3e38)
__device__ __align__(16) float4 g_t3a[NS * NSLOT];       // (b1, b2, b3, i1-bits)
__device__ int g_t3i[NS * NSLOT];                        // i2
__device__ unsigned g_maxHb = 0;                         // max_k ||h_b|| (float bits)
__device__ unsigned g_maxRb = 0;                         // max_k ||r_b||
__device__ int g_fcount;
__device__ int g_flist[NS];
__device__ unsigned long long g_bestu64[NS];
__device__ int   g_idx[NS];
__device__ float g_partial[1024];
__device__ unsigned g_done;

// ---------------------------------------------------------------------------
__device__ __forceinline__ uint32_t smem_u32(const void* p) {
    uint32_t a;
    asm("{ .reg .u64 t; cvta.to.shared.u64 t, %1; cvt.u32.u64 %0, t; }"
        : "=r"(a) : "l"(p));
    return a;
}
__device__ __forceinline__ void cp16(uint32_t daddr, const void* src) {
    asm volatile("cp.async.cg.shared.global [%0], [%1], 16;"
                 :: "r"(daddr), "l"(src) : "memory");
}
#define CP_COMMIT() asm volatile("cp.async.commit_group;" ::: "memory")

#define LDSM4(R, addr)                                                        \
    asm volatile("ldmatrix.sync.aligned.m8n8.x4.shared.b16 {%0,%1,%2,%3}, [%4];" \
                 : "=r"((R)[0]), "=r"((R)[1]), "=r"((R)[2]), "=r"((R)[3])     \
                 : "r"(addr))

#define MMA(D, A, B0, B1)                                                     \
    asm volatile("mma.sync.aligned.m16n8k16.row.col.f32.f16.f16.f32 "         \
                 "{%0,%1,%2,%3}, {%4,%5,%6,%7}, {%8,%9}, {%0,%1,%2,%3};"      \
                 : "+f"((D)[0]), "+f"((D)[1]), "+f"((D)[2]), "+f"((D)[3])     \
                 : "r"((A)[0]), "r"((A)[1]), "r"((A)[2]), "r"((A)[3]),        \
                   "r"(B0), "r"(B1))

__device__ __forceinline__ unsigned pk2h(float a, float b) {
    __half2 t = __floats2half2_rn(a, b);
    return *reinterpret_cast<unsigned*>(&t);
}
__device__ __forceinline__ unsigned enc_f(float f) {
    unsigned s = __float_as_uint(f);
    return (s & 0x80000000u) ? ~s : (s | 0x80000000u);
}
// partition for GRID2=296: 48 CTAs of 35 units, 248 of 34
__device__ __forceinline__ int cta_of(int u) {
    return (u < 48 * 35) ? (u / 35) : (48 + (u - 48 * 35) / 34);
}

__device__ __forceinline__ bool betteri(float v, int i, float w, int j) {
    return v > w || (v == w && i < j);
}
// merge sorted top-3 record (v1,i1,v2,i2,v3) with (c1,j1,c2,j2,c3); disjoint
// index sets; first-index tie rule; v3 needs no index.
__device__ __forceinline__ void merge3(float& v1, int& i1, float& v2, int& i2,
                                       float& v3, float c1, int j1, float c2,
                                       int j2, float c3) {
    if (betteri(c1, j1, v1, i1)) {
        if (betteri(v1, i1, c2, j2)) {
            v3 = fmaxf(c2, v2);
            v2 = v1; i2 = i1;
        } else {
            v3 = fmaxf(c3, v1);
            v2 = c2; i2 = j2;
        }
        v1 = c1; i1 = j1;
    } else {
        if (betteri(c1, j1, v2, i2)) {
            v3 = fmaxf(v2, c2);
            v2 = c1; i2 = j1;
        } else {
            v3 = fmaxf(v3, c1);
        }
    }
}

// ---------------------------------------------------------------------------
// prep: transpose cm per 32-cluster sub-tile; (hi, mid) fp16 B image; cmT;
// h_k; per-k norm maxes; zero g_t3a/g_t3i / g_fcount / g_done. grid = 316x256.
// ---------------------------------------------------------------------------
__global__ void prepB_kernel(const float* __restrict__ cm) {
    __shared__ float st[32][132];
    const int t = blockIdx.x >> 2;
    const int sub = blockIdx.x & 3;
    const int kbase = t * KT + sub * 32;
    const int tid = threadIdx.x;

    int gtid = blockIdx.x * 256 + tid;
    if (gtid < NS * NSLOT) {
        g_t3a[gtid] = make_float4(-3.4e38f, -3.4e38f, -3.4e38f,
                                  __int_as_float(0));
        g_t3i[gtid] = 0;
    }
    if (gtid == 0) { g_fcount = 0; g_done = 0; }

    if (kbase + 32 <= KK) {
#pragma unroll
        for (int i = 0; i < 4; i++) {
            int it = tid + i * 256;
            int d = it >> 3;
            int k4 = (it & 7) * 4;
            float4 v = *reinterpret_cast<const float4*>(cm + (size_t)d * KK + kbase + k4);
            st[k4 + 0][d] = v.x;
            st[k4 + 1][d] = v.y;
            st[k4 + 2][d] = v.z;
            st[k4 + 3][d] = v.w;
        }
    } else {
#pragma unroll
        for (int i = 0; i < 16; i++) {
            int it = tid + i * 256;
            int d = it >> 5;
            int k = it & 31;
            st[k][d] = (kbase + k < KK) ? cm[(size_t)d * KK + kbase + k] : 0.f;
        }
    }
    __syncthreads();

    // per-k: h_k, ||h_b||, ||r_b||
    {
        int n = tid >> 3, part = tid & 7;
        float sm = 0.f, sh2 = 0.f, sr2 = 0.f;
#pragma unroll
        for (int j = 0; j < 16; j++) {
            float v = st[n][part * 16 + j];
            float h = __half2float(__float2half_rn(v));
            float r = v - h;
            sm = fmaf(v, v, sm);
            sh2 = fmaf(h, h, sh2);
            sr2 = fmaf(r, r, sr2);
        }
#pragma unroll
        for (int off = 4; off; off >>= 1) {
            sm += __shfl_down_sync(0xffffffffu, sm, off);
            sh2 += __shfl_down_sync(0xffffffffu, sh2, off);
            sr2 += __shfl_down_sync(0xffffffffu, sr2, off);
        }
        if (part == 0) {
            if (kbase + n < KK) {
                g_h[kbase + n] = 0.5f * sm;
                atomicMax(&g_maxHb, __float_as_uint(sqrtf(sh2)));
                atomicMax(&g_maxRb, __float_as_uint(sqrtf(sr2)));
            } else {
                g_h[kbase + n] = -3.0e38f;
            }
        }
    }

    // (hi, mid) fp16 split, swizzled image
#pragma unroll
    for (int i = 0; i < 2; i++) {
        int it = tid + i * 256;
        int n = it >> 4;
        int c = it & 15;
        uint4 H, M;
        uint32_t* hp = &H.x; uint32_t* mp = &M.x;
#pragma unroll
        for (int j = 0; j < 4; j++) {
            float v0 = st[n][c * 8 + 2 * j];
            float v1 = st[n][c * 8 + 2 * j + 1];
            __half h0 = __float2half_rn(v0);
            __half h1 = __float2half_rn(v1);
            float r0 = v0 - __half2float(h0);
            float r1 = v1 - __half2float(h1);
            hp[j] = pk2h(v0, v1);
            mp[j] = pk2h(r0, r1);
        }
        int r = sub * 32 + n;
        int ci = r * 16 + (c ^ (r & 7));
        size_t base = (size_t)t * 4096 + ci;
        g_B4[base]        = H;
        g_B4[base + 2048] = M;
    }

    // transposed fp32 copy
#pragma unroll
    for (int i = 0; i < 4; i++) {
        int it = tid + i * 256;
        int n = it >> 5;
        int d4 = (it & 31) * 4;
        float4 w = make_float4(st[n][d4], st[n][d4 + 1], st[n][d4 + 2], st[n][d4 + 3]);
        *reinterpret_cast<float4*>(g_cmT + (size_t)(kbase + n) * DD + d4) = w;
    }
}

// ---------------------------------------------------------------------------
__device__ __forceinline__ void stageB_hi(uint32_t sb, int tid, int kc, int buf) {
    const uint4* src = g_B4 + (size_t)kc * 4096;   // hi split = first 2048 uint4
    uint32_t dst = sb + OFF_B + (uint32_t)buf * BUFB;
#pragma unroll
    for (int i = 0; i < 8; i++)
        cp16(dst + (uint32_t)(tid + i * 256) * 16, src + tid + i * 256);
    if (tid < 32)
        cp16(sb + OFF_H + (uint32_t)buf * 512 + (uint32_t)tid * 16,
             (const char*)g_h + (size_t)kc * 512 + (size_t)tid * 16);
    CP_COMMIT();
}

__device__ __forceinline__ void buildA_hi(char* smem, const float* __restrict__ x,
                                          int n0, int tid) {
    const int row = tid >> 1;
    const int c0 = (tid & 1) * 8;
    const float4* xr = reinterpret_cast<const float4*>(x + (size_t)(n0 + row) * DD);
    uint4* As = reinterpret_cast<uint4*>(smem + OFF_A);
#pragma unroll
    for (int c = 0; c < 8; c++) {
        float4 p = xr[(c0 + c) * 2];
        float4 q = xr[(c0 + c) * 2 + 1];
        uint4 H;
        H.x = pk2h(p.x, p.y);
        H.y = pk2h(p.z, p.w);
        H.z = pk2h(q.x, q.y);
        H.w = pk2h(q.z, q.w);
        As[row * 16 + ((c0 + c) ^ (row & 7))] = H;
    }
}

// merge CTA-local top-3 and publish slot for sample tile st_
__device__ void flush_fn(char* smem, int st_, int bid, const float* b1v,
                         const int* i1v, const float* b2v, const int* i2v,
                         const float* b3v, int tid, int lane, int mwarp,
                         int nwarp) {
    float* sb1 = reinterpret_cast<float*>(smem);
    int*   si1 = reinterpret_cast<int*>(smem + 2048);
    float* sb2 = reinterpret_cast<float*>(smem + 4096);
    int*   si2 = reinterpret_cast<int*>(smem + 6144);
    float* sb3 = reinterpret_cast<float*>(smem + 8192);
    __syncthreads();
#pragma unroll
    for (int s = 0; s < 8; s++) {
        float V1 = b1v[s]; int I1 = i1v[s];
        float V2 = b2v[s]; int I2 = i2v[s];
        float V3 = b3v[s];
#pragma unroll
        for (int off = 1; off < 4; off <<= 1) {
            float c1 = __shfl_xor_sync(0xffffffffu, V1, off);
            int   j1 = __shfl_xor_sync(0xffffffffu, I1, off);
            float c2 = __shfl_xor_sync(0xffffffffu, V2, off);
            int   j2 = __shfl_xor_sync(0xffffffffu, I2, off);
            float c3 = __shfl_xor_sync(0xffffffffu, V3, off);
            merge3(V1, I1, V2, I2, V3, c1, j1, c2, j2, c3);
        }
        if ((lane & 3) == 0) {
            int row = mwarp * 64 + (s >> 1) * 16 + (s & 1) * 8 + (lane >> 2);
            sb1[row * 4 + nwarp] = V1;
            si1[row * 4 + nwarp] = I1;
            sb2[row * 4 + nwarp] = V2;
            si2[row * 4 + nwarp] = I2;
            sb3[row * 4 + nwarp] = V3;
        }
    }
    __syncthreads();
    if (tid < 128) {
        float V1 = sb1[tid * 4]; int I1 = si1[tid * 4];
        float V2 = sb2[tid * 4]; int I2 = si2[tid * 4];
        float V3 = sb3[tid * 4];
#pragma unroll
        for (int w = 1; w < 4; w++) {
            merge3(V1, I1, V2, I2, V3,
                   sb1[tid * 4 + w], si1[tid * 4 + w],
                   sb2[tid * 4 + w], si2[tid * 4 + w],
                   sb3[tid * 4 + w]);
        }
        int slot = bid - cta_of(st_ * NT2);
        int gi = (st_ * TM + tid) * NSLOT + slot;
        g_t3a[gi] = make_float4(V1, V2, V3, __int_as_float(I1));
        g_t3i[gi] = I2;
    }
    __syncthreads();
}

// ---------------------------------------------------------------------------
// phase 1: persistent 296 CTAs (2/SM); 1-product hh GEMM + running top-3.
// ---------------------------------------------------------------------------
__global__ void __launch_bounds__(256, 2)
vq_main(const float* __restrict__ x) {
    extern __shared__ __align__(1024) char smem[];
    const uint32_t sb = smem_u32(smem);
    const int tid = threadIdx.x;
    const int wid = tid >> 5;
    const int lane = tid & 31;
    const int l8 = lane & 7;
    const int g = lane >> 3;
    const int mwarp = wid >> 2;
    const int nwarp = wid & 3;
    const int bid = blockIdx.x;

    const int start = bid * 34 + min(bid, 48);
    const int count = 34 + (bid < 48 ? 1 : 0);

    int cur_st = start / NT2;
    stageB_hi(sb, tid, start - cur_st * NT2, 0);
    buildA_hi(smem, x, cur_st * TM, tid);

    const uint32_t AQ  = sb + OFF_A + (uint32_t)mwarp * 16384u
                       + (uint32_t)l8 * 272 + ((uint32_t)(g & 1) << 11);
    const uint32_t gxa = (uint32_t)(g >> 1) << 4;
    const uint32_t gxb = (uint32_t)(g & 1) << 4;
    const uint32_t BQg = (uint32_t)nwarp * 8192u
                       + ((uint32_t)(g >> 1) << 11) + (uint32_t)l8 * 272;

    float b1v[8], b2v[8], b3v[8];
    int   i1v[8], i2v[8];
#pragma unroll
    for (int i = 0; i < 8; i++) {
        b1v[i] = -3.4e38f; b2v[i] = -3.4e38f; b3v[i] = -3.4e38f;
        i1v[i] = 0; i2v[i] = 0;
    }

    for (int i = 0; i < count; i++) {
        const int u = start + i;
        const int stt = u / NT2;
        const int kc = u - stt * NT2;
        const int b = i & 1;

        if (stt != cur_st) {
            flush_fn(smem, cur_st, bid, b1v, i1v, b2v, i2v, b3v,
                     tid, lane, mwarp, nwarp);
            buildA_hi(smem, x, stt * TM, tid);
            cur_st = stt;
#pragma unroll
            for (int s = 0; s < 8; s++) {
                b1v[s] = -3.4e38f; b2v[s] = -3.4e38f; b3v[s] = -3.4e38f;
                i1v[s] = 0; i2v[s] = 0;
            }
        }

        if (i + 1 < count) {
            const int u2 = start + i + 1;
            stageB_hi(sb, tid, u2 - (u2 / NT2) * NT2, (i + 1) & 1);
            asm volatile("cp.async.wait_group 1;" ::: "memory");
        } else {
            asm volatile("cp.async.wait_group 0;" ::: "memory");
        }
        __syncthreads();

        const uint32_t Bt = sb + OFF_B + (uint32_t)b * BUFB + BQg;
        float acc[4][4][4];
#pragma unroll
        for (int ma = 0; ma < 4; ma++)
#pragma unroll
            for (int nn = 0; nn < 4; nn++)
#pragma unroll
                for (int r = 0; r < 4; r++) acc[ma][nn][r] = 0.f;

#pragma unroll
        for (int ks = 0; ks < 8; ks++) {
            const uint32_t kxa = ((uint32_t)ks << 5) | gxa;
            const uint32_t kxb = ((uint32_t)ks << 5) | gxb;
            uint32_t a[4][4];
            uint32_t bf[2][4];
#pragma unroll
            for (int ma = 0; ma < 4; ma++)
                LDSM4(a[ma], (AQ + (uint32_t)ma * 4096) ^ kxa);
#pragma unroll
            for (int nb = 0; nb < 2; nb++)
                LDSM4(bf[nb], (Bt + (uint32_t)nb * 4096) ^ kxb);
#pragma unroll
            for (int ma = 0; ma < 4; ma++)
#pragma unroll
                for (int nn = 0; nn < 4; nn++)
                    MMA(acc[ma][nn], a[ma],
                        bf[nn >> 1][2 * (nn & 1)], bf[nn >> 1][2 * (nn & 1) + 1]);
        }

        const float* hb = reinterpret_cast<const float*>(smem + OFF_H + b * 512);
        const int kbase = kc * KT + nwarp * 32 + (lane & 3) * 2;
#pragma unroll
        for (int ma = 0; ma < 4; ma++) {
            float c0[8], c1[8];
#pragma unroll
            for (int nn = 0; nn < 4; nn++) {
                int hi0 = nwarp * 32 + nn * 8 + (lane & 3) * 2;
                float h0 = hb[hi0], h1 = hb[hi0 + 1];
                c0[2 * nn]     = h0 - acc[ma][nn][0];
                c0[2 * nn + 1] = h1 - acc[ma][nn][1];
                c1[2 * nn]     = h0 - acc[ma][nn][2];
                c1[2 * nn + 1] = h1 - acc[ma][nn][3];
            }
#pragma unroll
            for (int rh = 0; rh < 2; rh++) {
                const float* cc = rh ? c1 : c0;
                const int s = 2 * ma + rh;
                float gm = cc[0];
#pragma unroll
                for (int q = 1; q < 8; q++) gm = fmaxf(gm, cc[q]);
                if (gm > b3v[s]) {
#pragma unroll
                    for (int q = 0; q < 8; q++) {
                        float d = cc[q];
                        int k = kbase + (q >> 1) * 8 + (q & 1);
                        if (d > b1v[s]) {
                            b3v[s] = b2v[s];
                            b2v[s] = b1v[s]; i2v[s] = i1v[s];
                            b1v[s] = d; i1v[s] = k;
                        } else if (d > b2v[s]) {
                            b3v[s] = b2v[s];
                            b2v[s] = d; i2v[s] = k;
                        } else {
                            b3v[s] = fmaxf(b3v[s], d);
                        }
                    }
                }
            }
        }
        __syncthreads();
    }

    flush_fn(smem, cur_st, bid, b1v, i1v, b2v, i2v, b3v, tid, lane, mwarp, nwarp);
}

// ---------------------------------------------------------------------------
// decision with DOUBLE exact anchor: merge top-3 records, compute exact fp32
// ranks for i1 AND i2, winner by exact compare (first-index ties), certify
// against B3:  exact_w - B3 > E  (all other k provably below). grid=2048x256.
// ---------------------------------------------------------------------------
__global__ void decision_kernel(const float* __restrict__ x) {
    const int lane = threadIdx.x & 31;
    const int n = blockIdx.x * 8 + (threadIdx.x >> 5);
    float4 xv = reinterpret_cast<const float4*>(x)[n * 32 + lane];
    float sh2 = 0.f, sr2 = 0.f;
    float vv[4] = {xv.x, xv.y, xv.z, xv.w};
#pragma unroll
    for (int j = 0; j < 4; j++) {
        float h = __half2float(__float2half_rn(vv[j]));
        float r = vv[j] - h;
        sh2 = fmaf(h, h, sh2);
        sr2 = fmaf(r, r, sr2);
    }
#pragma unroll
    for (int off = 16; off; off >>= 1) {
        sh2 += __shfl_xor_sync(0xffffffffu, sh2, off);
        sr2 += __shfl_xor_sync(0xffffffffu, sr2, off);
    }

    float B1 = 0.f, B2 = 0.f, B3 = 0.f;
    int I1 = 0, I2 = 0;
    if (lane == 0) {
        float4 t0 = g_t3a[n * NSLOT + 0];
        B1 = t0.x; B2 = t0.y; B3 = t0.z;
        I1 = __float_as_int(t0.w);
        I2 = g_t3i[n * NSLOT + 0];
#pragma unroll
        for (int sl = 1; sl < NSLOT; sl++) {
            float4 tv = g_t3a[n * NSLOT + sl];
            merge3(B1, I1, B2, I2, B3,
                   tv.x, __float_as_int(tv.w), tv.y, g_t3i[n * NSLOT + sl], tv.z);
        }
    }
    I1 = __shfl_sync(0xffffffffu, I1, 0);
    I2 = __shfl_sync(0xffffffffu, I2, 0);

    // warp-cooperative exact fp32 dots for both anchors
    float4 c1v = *reinterpret_cast<const float4*>(g_cmT + (size_t)I1 * DD + lane * 4);
    float4 c2v = *reinterpret_cast<const float4*>(g_cmT + (size_t)I2 * DD + lane * 4);
    float dp1 = 0.f, dp2 = 0.f;
    dp1 = fmaf(xv.x, c1v.x, dp1); dp2 = fmaf(xv.x, c2v.x, dp2);
    dp1 = fmaf(xv.y, c1v.y, dp1); dp2 = fmaf(xv.y, c2v.y, dp2);
    dp1 = fmaf(xv.z, c1v.z, dp1); dp2 = fmaf(xv.z, c2v.z, dp2);
    dp1 = fmaf(xv.w, c1v.w, dp1); dp2 = fmaf(xv.w, c2v.w, dp2);
#pragma unroll
    for (int off = 16; off; off >>= 1) {
        dp1 += __shfl_xor_sync(0xffffffffu, dp1, off);
        dp2 += __shfl_xor_sync(0xffffffffu, dp2, off);
    }

    if (lane == 0) {
        float Hbm = __uint_as_float(g_maxHb);
        float Rbm = __uint_as_float(g_maxRb);
        float nh = sqrtf(sh2), nr = sqrtf(sr2);
        float E = (nh * Rbm + nr * Hbm + nr * Rbm) * 1.001f + 6e-3f;
        float e1 = g_h[I1] - dp1;
        float e2 = g_h[I2] - dp2;

        int w; float ew;
        if (betteri(e2, I2, e1, I1)) { w = I2; ew = e2; }
        else                         { w = I1; ew = e1; }

        if (ew - B3 > E) {
            g_idx[n] = w;
        } else {
            g_idx[n] = -1;
            g_bestu64[n] = 0ull;
            int p = atomicAdd(&g_fcount, 1);
            g_flist[p] = n;
        }
    }
}

// ---------------------------------------------------------------------------
// fallback2: 3-product MMA rescan of flagged samples (gathered A tiles).
// Persistent GRID CTAs over ceil(fcount/128) x 79 units. atomicMax publish.
// ---------------------------------------------------------------------------
__global__ void __launch_bounds__(256, 1)
fallback2_kernel(const float* __restrict__ x) {
    extern __shared__ __align__(1024) char smem[];
    const uint32_t sb = smem_u32(smem);
    const int tid = threadIdx.x;
    const int wid = tid >> 5;
    const int lane = tid & 31;
    const int l8 = lane & 7;
    const int gg = lane >> 3;
    const int mwarp = wid >> 2;
    const int nwarp = wid & 3;

    const int fcount = g_fcount;
    if (fcount == 0) return;
    const int nG = (fcount + 127) >> 7;
    const int total = nG * NT2;

    int* sids = reinterpret_cast<int*>(smem + F2_OFF_S);

    const uint32_t AQ  = sb + F2_OFF_A + (uint32_t)mwarp * 16384u
                       + (uint32_t)l8 * 272 + ((uint32_t)(gg & 1) << 11);
    const uint32_t gxa = (uint32_t)(gg >> 1) << 4;
    const uint32_t gxb = (uint32_t)(gg & 1) << 4;
    const uint32_t BQg = sb + F2_OFF_B + (uint32_t)nwarp * 8192u
                       + ((uint32_t)(gg >> 1) << 11) + (uint32_t)l8 * 272;

    for (int u = blockIdx.x; u < total; u += GRID) {
        const int gi = u / NT2;
        const int kt = u - gi * NT2;
        __syncthreads();

        if (tid < 128) {
            int fi = gi * 128 + tid;
            sids[tid] = (fi < fcount) ? g_flist[fi] : -1;
        }
        {
            const uint4* src = g_B4 + (size_t)kt * 4096;
#pragma unroll
            for (int i = 0; i < 16; i++)
                cp16(sb + F2_OFF_B + (uint32_t)(tid + i * 256) * 16,
                     src + tid + i * 256);
            if (tid < 32)
                cp16(sb + F2_OFF_H + (uint32_t)tid * 16,
                     (const char*)g_h + (size_t)kt * 512 + (size_t)tid * 16);
            CP_COMMIT();
        }
        __syncthreads();

        {
            const int row = tid >> 1;
            const int c0 = (tid & 1) * 8;
            const int n = sids[row];
            uint4* As = reinterpret_cast<uint4*>(smem + F2_OFF_A);
            if (n >= 0) {
                const float4* xr =
                    reinterpret_cast<const float4*>(x + (size_t)n * DD);
#pragma unroll
                for (int c = 0; c < 8; c++) {
                    float4 p = xr[(c0 + c) * 2];
                    float4 q = xr[(c0 + c) * 2 + 1];
                    float v[8] = {p.x, p.y, p.z, p.w, q.x, q.y, q.z, q.w};
                    uint4 H, M;
                    uint32_t* hp = &H.x; uint32_t* mp = &M.x;
#pragma unroll
                    for (int j = 0; j < 4; j++) {
                        float v0 = v[2 * j], v1 = v[2 * j + 1];
                        __half h0 = __float2half_rn(v0);
                        __half h1 = __float2half_rn(v1);
                        float r0 = v0 - __half2float(h0);
                        float r1 = v1 - __half2float(h1);
                        hp[j] = pk2h(v0, v1);
                        mp[j] = pk2h(r0, r1);
                    }
                    int ci = row * 16 + ((c0 + c) ^ (row & 7));
                    As[ci] = H;
                    As[ci + 2048] = M;
                }
            } else {
                uint4 Z = make_uint4(0, 0, 0, 0);
#pragma unroll
                for (int c = 0; c < 8; c++) {
                    int ci = row * 16 + ((c0 + c) ^ (row & 7));
                    As[ci] = Z;
                    As[ci + 2048] = Z;
                }
            }
        }
        asm volatile("cp.async.wait_group 0;" ::: "memory");
        __syncthreads();

        float acc[4][4][4];
#pragma unroll
        for (int ma = 0; ma < 4; ma++)
#pragma unroll
            for (int nn = 0; nn < 4; nn++)
#pragma unroll
                for (int r = 0; r < 4; r++) acc[ma][nn][r] = 0.f;

#pragma unroll
        for (int ks = 0; ks < 8; ks++) {
            const uint32_t kxa = ((uint32_t)ks << 5) | gxa;
            const uint32_t kxb = ((uint32_t)ks << 5) | gxb;
            uint32_t a[2][4][4];
            uint32_t bf[2][2][4];
#pragma unroll
            for (int s = 0; s < 2; s++)
#pragma unroll
                for (int ma = 0; ma < 4; ma++)
                    LDSM4(a[s][ma],
                          (AQ + (uint32_t)s * 32768 + (uint32_t)ma * 4096) ^ kxa);
#pragma unroll
            for (int s = 0; s < 2; s++)
#pragma unroll
                for (int nb = 0; nb < 2; nb++)
                    LDSM4(bf[s][nb],
                          (BQg + (uint32_t)s * 32768 + (uint32_t)nb * 4096) ^ kxb);

            const int PA[3] = {0, 0, 1};
            const int PB[3] = {0, 1, 0};
#pragma unroll
            for (int p = 0; p < 3; p++)
#pragma unroll
                for (int ma = 0; ma < 4; ma++)
#pragma unroll
                    for (int nn = 0; nn < 4; nn++)
                        MMA(acc[ma][nn], a[PA[p]][ma],
                            bf[PB[p]][nn >> 1][2 * (nn & 1)],
                            bf[PB[p]][nn >> 1][2 * (nn & 1) + 1]);
        }

        const float* hb = reinterpret_cast<const float*>(smem + F2_OFF_H);
        float* sbv = reinterpret_cast<float*>(smem + F2_OFF_A);
        int*   siv = reinterpret_cast<int*>(smem + F2_OFF_A + 2048);
        __syncthreads();
#pragma unroll
        for (int ma = 0; ma < 4; ma++)
#pragma unroll
            for (int rh = 0; rh < 2; rh++) {
                float bv = -3.4e38f;
                int bix = 0;
#pragma unroll
                for (int nn = 0; nn < 4; nn++) {
                    int hi0 = nwarp * 32 + nn * 8 + (lane & 3) * 2;
                    float d0 = hb[hi0] - acc[ma][nn][2 * rh];
                    float d1 = hb[hi0 + 1] - acc[ma][nn][2 * rh + 1];
                    int k0 = kt * KT + hi0;
                    if (d0 > bv) { bv = d0; bix = k0; }
                    if (d1 > bv) { bv = d1; bix = k0 + 1; }
                }
#pragma unroll
                for (int off = 1; off < 4; off <<= 1) {
                    float ov = __shfl_xor_sync(0xffffffffu, bv, off);
                    int   oi = __shfl_xor_sync(0xffffffffu, bix, off);
                    if (ov > bv || (ov == bv && oi < bix)) { bv = ov; bix = oi; }
                }
                if ((lane & 3) == 0) {
                    int row = mwarp * 64 + ma * 16 + rh * 8 + (lane >> 2);
                    sbv[row * 4 + nwarp] = bv;
                    siv[row * 4 + nwarp] = bix;
                }
            }
        __syncthreads();
        if (tid < 128) {
            float bv = sbv[tid * 4];
            int bix = siv[tid * 4];
#pragma unroll
            for (int w = 1; w < 4; w++) {
                float v = sbv[tid * 4 + w];
                int ix = siv[tid * 4 + w];
                if (v > bv || (v == bv && ix < bix)) { bv = v; bix = ix; }
            }
            int sid = sids[tid];
            if (sid >= 0) {
                unsigned long long key =
                    ((unsigned long long)enc_f(bv) << 32)
                    | (unsigned long long)(0xFFFFFFFFu - (unsigned)bix);
                atomicMax(&g_bestu64[sid], key);
            }
        }
    }
}

// ---------------------------------------------------------------------------
// gather quantize + index output + MSE (last block folds final reduction)
// ---------------------------------------------------------------------------
__global__ void gather_kernel(const float* __restrict__ x,
                              float* __restrict__ out) {
    __shared__ float red[256];
    __shared__ bool last;
    const int tid = threadIdx.x;
    float* out_q = out;
    float* out_idx_f = out + (size_t)NS * DD;

    int gt = blockIdx.x * 256 + tid;
    if (gt < NS) {
        int ix = g_idx[gt];
        if (ix < 0)
            ix = (int)(0xFFFFFFFFu - (unsigned)(g_bestu64[gt] & 0xFFFFFFFFull));
        out_idx_f[gt] = (float)ix;
    }

    float local = 0.f;
    for (int e4 = blockIdx.x * 256 + tid; e4 < NS * DD / 4;
         e4 += gridDim.x * 256) {
        int n = e4 >> 5;
        int d4 = (e4 & 31) * 4;
        int ix = g_idx[n];
        if (ix < 0)
            ix = (int)(0xFFFFFFFFu - (unsigned)(g_bestu64[n] & 0xFFFFFFFFull));
        float4 q = *reinterpret_cast<const float4*>(g_cmT + (size_t)ix * DD + d4);
        float4 xv = reinterpret_cast<const float4*>(x)[e4];
        reinterpret_cast<float4*>(out_q)[e4] = q;
        float a = xv.x - q.x, b = xv.y - q.y, c = xv.z - q.z, d = xv.w - q.w;
        local = fmaf(a, a, local);
        local = fmaf(b, b, local);
        local = fmaf(c, c, local);
        local = fmaf(d, d, local);
    }
    red[tid] = local;
    __syncthreads();
    for (int s = 128; s; s >>= 1) {
        if (tid < s) red[tid] += red[tid + s];
        __syncthreads();
    }
    if (tid == 0) {
        g_partial[blockIdx.x] = red[0];
        __threadfence();
        unsigned t = atomicAdd(&g_done, 1u);
        last = (t == gridDim.x - 1);
    }
    __syncthreads();
    if (last) {
        __threadfence();
        volatile float* gp = g_partial;
        __shared__ double dred[256];
        double acc = 0.0;
        for (int i = tid; i < 1024; i += 256) acc += (double)gp[i];
        dred[tid] = acc;
        __syncthreads();
        for (int st = 128; st; st >>= 1) {
            if (tid < st) dred[tid] += dred[tid + st];
            __syncthreads();
        }
        if (tid == 0)
            out[(size_t)NS * DD + NS] =
                (float)(dred[0] / (double)((size_t)NS * DD));
    }
}

// ---------------------------------------------------------------------------
extern "C" void kernel_launch(void* const* d_in, const int* in_sizes, int n_in,
                              void* d_out, int out_size) {
    const float* x  = (const float*)d_in[0];   // [16384, 128]
    const float* cm = (const float*)d_in[1];   // [128, 10000]
    float* out = (float*)d_out;                // [quantize | index | diff]

    cudaFuncSetAttribute(vq_main,
                         cudaFuncAttributeMaxDynamicSharedMemorySize, SMEM_TOTAL);
    cudaFuncSetAttribute(fallback2_kernel,
                         cudaFuncAttributeMaxDynamicSharedMemorySize, F2_SMEM);

    prepB_kernel<<<NT2 * 4, 256>>>(cm);
    vq_main<<<GRID2, 256, SMEM_TOTAL>>>(x);
    decision_kernel<<<NS / 8, 256>>>(x);
    fallback2_kernel<<<GRID, 256, F2_SMEM>>>(x);
    gather_kernel<<<1024, 256>>>(x, out);
}

// round 17
// speedup vs baseline: 1.4548x; 1.4548x over previous
#include <cuda_runtime.h>
#include <cuda_fp16.h>
#include <cstdint>

#define NS   16384
#define DD   128
#define KK   10000
#define KT   128
#define NT2  79             // k-tiles; 79*128 = 10112
#define KPAD (NT2 * KT)
#define TM   128
#define GRID 148
#define GRID2 296           // vq_main: 2 CTAs/SM
#define NSLOT 4             // max CTAs covering one sample tile

// ---- vq_main smem layout (hi split only) ----
#define OFF_A  0            // 32768: x-tile hi split, swizzled fp16
#define OFF_B  32768        // 2 x 32768 buffers
#define BUFB   32768
#define OFF_H  98304        // 2 x 512
#define SMEM_TOTAL (OFF_H + 1024)

// ---- fallback2 smem layout (hi+mid splits) ----
#define F2_OFF_A 0          // 2 x 32768 (hi, mid)
#define F2_OFF_B 65536      // 65536 (hi|mid), single buffer
#define F2_OFF_H 131072     // 512
#define F2_OFF_S 131584     // 128 ints (sample ids)
#define F2_SMEM  (F2_OFF_S + 512)

__device__ uint4 g_B4[(size_t)NT2 * 4096];               // hi+mid swizzled B tiles
__device__ __align__(16) float g_cmT[(size_t)KPAD * DD]; // transposed means [k][d]
__device__ __align__(16) float g_h[KPAD];                // 0.5*||m||^2 (pad -> -3e38)
__device__ __align__(16) float4 g_top2[NS * NSLOT];      // per (sample, slot): b1,b2,i1
__device__ unsigned g_maxHb = 0;                         // max_k ||h_b|| (float bits)
__device__ unsigned g_maxRb = 0;                         // max_k ||r_b||
__device__ int g_fcount;
__device__ int g_flist[NS];
__device__ unsigned long long g_bestu64[NS];
__device__ int   g_idx[NS];
__device__ float g_partial[1024];
__device__ unsigned g_done;

// ---------------------------------------------------------------------------
__device__ __forceinline__ uint32_t smem_u32(const void* p) {
    uint32_t a;
    asm("{ .reg .u64 t; cvta.to.shared.u64 t, %1; cvt.u32.u64 %0, t; }"
        : "=r"(a) : "l"(p));
    return a;
}
__device__ __forceinline__ void cp16(uint32_t daddr, const void* src) {
    asm volatile("cp.async.cg.shared.global [%0], [%1], 16;"
                 :: "r"(daddr), "l"(src) : "memory");
}
#define CP_COMMIT() asm volatile("cp.async.commit_group;" ::: "memory")

#define LDSM4(R, addr)                                                        \
    asm volatile("ldmatrix.sync.aligned.m8n8.x4.shared.b16 {%0,%1,%2,%3}, [%4];" \
                 : "=r"((R)[0]), "=r"((R)[1]), "=r"((R)[2]), "=r"((R)[3])     \
                 : "r"(addr))

#define MMA(D, A, B0, B1)                                                     \
    asm volatile("mma.sync.aligned.m16n8k16.row.col.f32.f16.f16.f32 "         \
                 "{%0,%1,%2,%3}, {%4,%5,%6,%7}, {%8,%9}, {%0,%1,%2,%3};"      \
                 : "+f"((D)[0]), "+f"((D)[1]), "+f"((D)[2]), "+f"((D)[3])     \
                 : "r"((A)[0]), "r"((A)[1]), "r"((A)[2]), "r"((A)[3]),        \
                   "r"(B0), "r"(B1))

__device__ __forceinline__ unsigned pk2h(float a, float b) {
    __half2 t = __floats2half2_rn(a, b);
    return *reinterpret_cast<unsigned*>(&t);
}
__device__ __forceinline__ unsigned enc_f(float f) {
    unsigned s = __float_as_uint(f);
    return (s & 0x80000000u) ? ~s : (s | 0x80000000u);
}
__device__ __forceinline__ bool betteri(float v, int i, float w, int j) {
    return v > w || (v == w && i < j);
}
// partition for GRID2=296: 48 CTAs of 35 units, 248 of 34
__device__ __forceinline__ int cta_of(int u) {
    return (u < 48 * 35) ? (u / 35) : (48 + (u - 48 * 35) / 34);
}

// ---------------------------------------------------------------------------
// prep: transpose cm per 32-cluster sub-tile; (hi, mid) fp16 B image; cmT;
// h_k; per-k norm maxes; zero g_top2 / g_fcount / g_done. grid = 316 x 256.
// ---------------------------------------------------------------------------
__global__ void prepB_kernel(const float* __restrict__ cm) {
    __shared__ float st[32][132];
    const int t = blockIdx.x >> 2;
    const int sub = blockIdx.x & 3;
    const int kbase = t * KT + sub * 32;
    const int tid = threadIdx.x;

    int gtid = blockIdx.x * 256 + tid;
    if (gtid < NS * NSLOT)
        g_top2[gtid] = make_float4(-3.4e38f, -3.4e38f, __int_as_float(0), 0.f);
    if (gtid == 0) { g_fcount = 0; g_done = 0; }

    if (kbase + 32 <= KK) {
#pragma unroll
        for (int i = 0; i < 4; i++) {
            int it = tid + i * 256;
            int d = it >> 3;
            int k4 = (it & 7) * 4;
            float4 v = *reinterpret_cast<const float4*>(cm + (size_t)d * KK + kbase + k4);
            st[k4 + 0][d] = v.x;
            st[k4 + 1][d] = v.y;
            st[k4 + 2][d] = v.z;
            st[k4 + 3][d] = v.w;
        }
    } else {
#pragma unroll
        for (int i = 0; i < 16; i++) {
            int it = tid + i * 256;
            int d = it >> 5;
            int k = it & 31;
            st[k][d] = (kbase + k < KK) ? cm[(size_t)d * KK + kbase + k] : 0.f;
        }
    }
    __syncthreads();

    // per-k: h_k, ||h_b||, ||r_b||
    {
        int n = tid >> 3, part = tid & 7;
        float sm = 0.f, sh2 = 0.f, sr2 = 0.f;
#pragma unroll
        for (int j = 0; j < 16; j++) {
            float v = st[n][part * 16 + j];
            float h = __half2float(__float2half_rn(v));
            float r = v - h;
            sm = fmaf(v, v, sm);
            sh2 = fmaf(h, h, sh2);
            sr2 = fmaf(r, r, sr2);
        }
#pragma unroll
        for (int off = 4; off; off >>= 1) {
            sm += __shfl_down_sync(0xffffffffu, sm, off);
            sh2 += __shfl_down_sync(0xffffffffu, sh2, off);
            sr2 += __shfl_down_sync(0xffffffffu, sr2, off);
        }
        if (part == 0) {
            if (kbase + n < KK) {
                g_h[kbase + n] = 0.5f * sm;
                atomicMax(&g_maxHb, __float_as_uint(sqrtf(sh2)));
                atomicMax(&g_maxRb, __float_as_uint(sqrtf(sr2)));
            } else {
                g_h[kbase + n] = -3.0e38f;
            }
        }
    }

    // (hi, mid) fp16 split, swizzled image
#pragma unroll
    for (int i = 0; i < 2; i++) {
        int it = tid + i * 256;
        int n = it >> 4;
        int c = it & 15;
        uint4 H, M;
        uint32_t* hp = &H.x; uint32_t* mp = &M.x;
#pragma unroll
        for (int j = 0; j < 4; j++) {
            float v0 = st[n][c * 8 + 2 * j];
            float v1 = st[n][c * 8 + 2 * j + 1];
            __half h0 = __float2half_rn(v0);
            __half h1 = __float2half_rn(v1);
            float r0 = v0 - __half2float(h0);
            float r1 = v1 - __half2float(h1);
            hp[j] = pk2h(v0, v1);
            mp[j] = pk2h(r0, r1);
        }
        int r = sub * 32 + n;
        int ci = r * 16 + (c ^ (r & 7));
        size_t base = (size_t)t * 4096 + ci;
        g_B4[base]        = H;
        g_B4[base + 2048] = M;
    }

    // transposed fp32 copy
#pragma unroll
    for (int i = 0; i < 4; i++) {
        int it = tid + i * 256;
        int n = it >> 5;
        int d4 = (it & 31) * 4;
        float4 w = make_float4(st[n][d4], st[n][d4 + 1], st[n][d4 + 2], st[n][d4 + 3]);
        *reinterpret_cast<float4*>(g_cmT + (size_t)(kbase + n) * DD + d4) = w;
    }
}

// ---------------------------------------------------------------------------
__device__ __forceinline__ void stageB_hi(uint32_t sb, int tid, int kc, int buf) {
    const uint4* src = g_B4 + (size_t)kc * 4096;   // hi split = first 2048 uint4
    uint32_t dst = sb + OFF_B + (uint32_t)buf * BUFB;
#pragma unroll
    for (int i = 0; i < 8; i++)
        cp16(dst + (uint32_t)(tid + i * 256) * 16, src + tid + i * 256);
    if (tid < 32)
        cp16(sb + OFF_H + (uint32_t)buf * 512 + (uint32_t)tid * 16,
             (const char*)g_h + (size_t)kc * 512 + (size_t)tid * 16);
    CP_COMMIT();
}

__device__ __forceinline__ void buildA_hi(char* smem, const float* __restrict__ x,
                                          int n0, int tid) {
    const int row = tid >> 1;
    const int c0 = (tid & 1) * 8;
    const float4* xr = reinterpret_cast<const float4*>(x + (size_t)(n0 + row) * DD);
    uint4* As = reinterpret_cast<uint4*>(smem + OFF_A);
#pragma unroll
    for (int c = 0; c < 8; c++) {
        float4 p = xr[(c0 + c) * 2];
        float4 q = xr[(c0 + c) * 2 + 1];
        uint4 H;
        H.x = pk2h(p.x, p.y);
        H.y = pk2h(p.z, p.w);
        H.z = pk2h(q.x, q.y);
        H.w = pk2h(q.z, q.w);
        As[row * 16 + ((c0 + c) ^ (row & 7))] = H;
    }
}

// top-2 merge
#define T2_MERGE(B1, I1, B2, c1, j1, c2)                          \
    do {                                                          \
        float _nb2 = fmaxf(fminf(B1, c1), fmaxf(B2, c2));         \
        bool _win = (c1 > B1) || (c1 == B1 && (j1) < (I1));       \
        if (_win) { B1 = c1; I1 = j1; }                           \
        B2 = _nb2;                                                \
    } while (0)

__device__ void flush_fn(char* smem, int st_, int bid, const float* b1v,
                         const int* i1v, const float* b2v, int tid, int lane,
                         int mwarp, int nwarp) {
    float* sb1 = reinterpret_cast<float*>(smem);
    int*   si1 = reinterpret_cast<int*>(smem + 2048);
    float* sb2 = reinterpret_cast<float*>(smem + 4096);
    __syncthreads();
#pragma unroll
    for (int s = 0; s < 8; s++) {
        float B1 = b1v[s]; int I1 = i1v[s]; float B2 = b2v[s];
#pragma unroll
        for (int off = 1; off < 4; off <<= 1) {
            float o1 = __shfl_xor_sync(0xffffffffu, B1, off);
            int   oi = __shfl_xor_sync(0xffffffffu, I1, off);
            float o2 = __shfl_xor_sync(0xffffffffu, B2, off);
            T2_MERGE(B1, I1, B2, o1, oi, o2);
        }
        if ((lane & 3) == 0) {
            int row = mwarp * 64 + (s >> 1) * 16 + (s & 1) * 8 + (lane >> 2);
            sb1[row * 4 + nwarp] = B1;
            si1[row * 4 + nwarp] = I1;
            sb2[row * 4 + nwarp] = B2;
        }
    }
    __syncthreads();
    if (tid < 128) {
        float B1 = sb1[tid * 4]; int I1 = si1[tid * 4]; float B2 = sb2[tid * 4];
#pragma unroll
        for (int w = 1; w < 4; w++) {
            float c1 = sb1[tid * 4 + w];
            int   j1 = si1[tid * 4 + w];
            float c2 = sb2[tid * 4 + w];
            T2_MERGE(B1, I1, B2, c1, j1, c2);
        }
        int slot = bid - cta_of(st_ * NT2);
        g_top2[(st_ * TM + tid) * NSLOT + slot] =
            make_float4(B1, B2, __int_as_float(I1), 0.f);
    }
    __syncthreads();
}

// ---------------------------------------------------------------------------
// phase 1: persistent 296 CTAs (2/SM); 1-product hh GEMM + running top-2.
// (byte-identical to the proven round-9/15 kernel)
// ---------------------------------------------------------------------------
__global__ void __launch_bounds__(256, 2)
vq_main(const float* __restrict__ x) {
    extern __shared__ __align__(1024) char smem[];
    const uint32_t sb = smem_u32(smem);
    const int tid = threadIdx.x;
    const int wid = tid >> 5;
    const int lane = tid & 31;
    const int l8 = lane & 7;
    const int g = lane >> 3;
    const int mwarp = wid >> 2;
    const int nwarp = wid & 3;
    const int bid = blockIdx.x;

    const int start = bid * 34 + min(bid, 48);
    const int count = 34 + (bid < 48 ? 1 : 0);

    int cur_st = start / NT2;
    stageB_hi(sb, tid, start - cur_st * NT2, 0);
    buildA_hi(smem, x, cur_st * TM, tid);

    const uint32_t AQ  = sb + OFF_A + (uint32_t)mwarp * 16384u
                       + (uint32_t)l8 * 272 + ((uint32_t)(g & 1) << 11);
    const uint32_t gxa = (uint32_t)(g >> 1) << 4;
    const uint32_t gxb = (uint32_t)(g & 1) << 4;
    const uint32_t BQg = (uint32_t)nwarp * 8192u
                       + ((uint32_t)(g >> 1) << 11) + (uint32_t)l8 * 272;

    float b1v[8], b2v[8];
    int   i1v[8];
#pragma unroll
    for (int i = 0; i < 8; i++) { b1v[i] = -3.4e38f; b2v[i] = -3.4e38f; i1v[i] = 0; }

    for (int i = 0; i < count; i++) {
        const int u = start + i;
        const int stt = u / NT2;
        const int kc = u - stt * NT2;
        const int b = i & 1;

        if (stt != cur_st) {
            flush_fn(smem, cur_st, bid, b1v, i1v, b2v, tid, lane, mwarp, nwarp);
            buildA_hi(smem, x, stt * TM, tid);
            cur_st = stt;
#pragma unroll
            for (int s = 0; s < 8; s++) { b1v[s] = -3.4e38f; b2v[s] = -3.4e38f; i1v[s] = 0; }
        }

        if (i + 1 < count) {
            const int u2 = start + i + 1;
            stageB_hi(sb, tid, u2 - (u2 / NT2) * NT2, (i + 1) & 1);
            asm volatile("cp.async.wait_group 1;" ::: "memory");
        } else {
            asm volatile("cp.async.wait_group 0;" ::: "memory");
        }
        __syncthreads();

        const uint32_t Bt = sb + OFF_B + (uint32_t)b * BUFB + BQg;
        float acc[4][4][4];
#pragma unroll
        for (int ma = 0; ma < 4; ma++)
#pragma unroll
            for (int nn = 0; nn < 4; nn++)
#pragma unroll
                for (int r = 0; r < 4; r++) acc[ma][nn][r] = 0.f;

#pragma unroll
        for (int ks = 0; ks < 8; ks++) {
            const uint32_t kxa = ((uint32_t)ks << 5) | gxa;
            const uint32_t kxb = ((uint32_t)ks << 5) | gxb;
            uint32_t a[4][4];
            uint32_t bf[2][4];
#pragma unroll
            for (int ma = 0; ma < 4; ma++)
                LDSM4(a[ma], (AQ + (uint32_t)ma * 4096) ^ kxa);
#pragma unroll
            for (int nb = 0; nb < 2; nb++)
                LDSM4(bf[nb], (Bt + (uint32_t)nb * 4096) ^ kxb);
#pragma unroll
            for (int ma = 0; ma < 4; ma++)
#pragma unroll
                for (int nn = 0; nn < 4; nn++)
                    MMA(acc[ma][nn], a[ma],
                        bf[nn >> 1][2 * (nn & 1)], bf[nn >> 1][2 * (nn & 1) + 1]);
        }

        const float* hb = reinterpret_cast<const float*>(smem + OFF_H + b * 512);
        const int kbase = kc * KT + nwarp * 32 + (lane & 3) * 2;
#pragma unroll
        for (int ma = 0; ma < 4; ma++) {
            float c0[8], c1[8];
#pragma unroll
            for (int nn = 0; nn < 4; nn++) {
                int hi0 = nwarp * 32 + nn * 8 + (lane & 3) * 2;
                float h0 = hb[hi0], h1 = hb[hi0 + 1];
                c0[2 * nn]     = h0 - acc[ma][nn][0];
                c0[2 * nn + 1] = h1 - acc[ma][nn][1];
                c1[2 * nn]     = h0 - acc[ma][nn][2];
                c1[2 * nn + 1] = h1 - acc[ma][nn][3];
            }
#pragma unroll
            for (int rh = 0; rh < 2; rh++) {
                const float* cc = rh ? c1 : c0;
                const int s = 2 * ma + rh;
                float gm = cc[0];
#pragma unroll
                for (int q = 1; q < 8; q++) gm = fmaxf(gm, cc[q]);
                if (gm > b2v[s]) {
#pragma unroll
                    for (int q = 0; q < 8; q++) {
                        float d = cc[q];
                        int k = kbase + (q >> 1) * 8 + (q & 1);
                        if (d > b1v[s]) { b2v[s] = b1v[s]; b1v[s] = d; i1v[s] = k; }
                        else b2v[s] = fmaxf(b2v[s], d);
                    }
                }
            }
        }
        __syncthreads();
    }

    flush_fn(smem, cur_st, bid, b1v, i1v, b2v, tid, lane, mwarp, nwarp);
}

// ---------------------------------------------------------------------------
// decision with PER-SLOT exact anchors: each of the NSLOT slot records covers
// a DISJOINT k-range; its i1 is that range's approx top. Exact fp32 dots for
// all 4 slot winners; winner = exact first-max; every non-anchor k in slot s
// satisfies approx(k) <= b2_s <= B2max, so certify  exact_w - B2max > E.
// Strictly tighter than the single-anchor test. grid = 2048 x 256.
// ---------------------------------------------------------------------------
__global__ void decision_kernel(const float* __restrict__ x) {
    const int lane = threadIdx.x & 31;
    const int n = blockIdx.x * 8 + (threadIdx.x >> 5);
    float4 xv = reinterpret_cast<const float4*>(x)[n * 32 + lane];
    float sh2 = 0.f, sr2 = 0.f;
    float vv[4] = {xv.x, xv.y, xv.z, xv.w};
#pragma unroll
    for (int j = 0; j < 4; j++) {
        float h = __half2float(__float2half_rn(vv[j]));
        float r = vv[j] - h;
        sh2 = fmaf(h, h, sh2);
        sr2 = fmaf(r, r, sr2);
    }
#pragma unroll
    for (int off = 16; off; off >>= 1) {
        sh2 += __shfl_xor_sync(0xffffffffu, sh2, off);
        sr2 += __shfl_xor_sync(0xffffffffu, sr2, off);
    }

    // lanes 0..3 each hold one slot record
    float b2s = -3.4e38f;
    int anc = 0;
    if (lane < NSLOT) {
        float4 tv = g_top2[n * NSLOT + lane];
        b2s = tv.y;
        anc = __float_as_int(tv.z);
    }
    // broadcast the 4 anchor indices
    int a0 = __shfl_sync(0xffffffffu, anc, 0);
    int a1 = __shfl_sync(0xffffffffu, anc, 1);
    int a2 = __shfl_sync(0xffffffffu, anc, 2);
    int a3 = __shfl_sync(0xffffffffu, anc, 3);

    // 4 warp-cooperative exact fp32 dots
    float4 c0 = *reinterpret_cast<const float4*>(g_cmT + (size_t)a0 * DD + lane * 4);
    float4 c1 = *reinterpret_cast<const float4*>(g_cmT + (size_t)a1 * DD + lane * 4);
    float4 c2 = *reinterpret_cast<const float4*>(g_cmT + (size_t)a2 * DD + lane * 4);
    float4 c3 = *reinterpret_cast<const float4*>(g_cmT + (size_t)a3 * DD + lane * 4);
    float d0 = 0.f, d1 = 0.f, d2 = 0.f, d3 = 0.f;
    d0 = fmaf(xv.x, c0.x, d0); d1 = fmaf(xv.x, c1.x, d1);
    d2 = fmaf(xv.x, c2.x, d2); d3 = fmaf(xv.x, c3.x, d3);
    d0 = fmaf(xv.y, c0.y, d0); d1 = fmaf(xv.y, c1.y, d1);
    d2 = fmaf(xv.y, c2.y, d2); d3 = fmaf(xv.y, c3.y, d3);
    d0 = fmaf(xv.z, c0.z, d0); d1 = fmaf(xv.z, c1.z, d1);
    d2 = fmaf(xv.z, c2.z, d2); d3 = fmaf(xv.z, c3.z, d3);
    d0 = fmaf(xv.w, c0.w, d0); d1 = fmaf(xv.w, c1.w, d1);
    d2 = fmaf(xv.w, c2.w, d2); d3 = fmaf(xv.w, c3.w, d3);
#pragma unroll
    for (int off = 16; off; off >>= 1) {
        d0 += __shfl_xor_sync(0xffffffffu, d0, off);
        d1 += __shfl_xor_sync(0xffffffffu, d1, off);
        d2 += __shfl_xor_sync(0xffffffffu, d2, off);
        d3 += __shfl_xor_sync(0xffffffffu, d3, off);
    }
    // B2max across slots (lanes 0..3)
    float bm = b2s;
#pragma unroll
    for (int off = 1; off < 4; off <<= 1)
        bm = fmaxf(bm, __shfl_xor_sync(0xffffffffu, bm, off));

    if (lane == 0) {
        float Hbm = __uint_as_float(g_maxHb);
        float Rbm = __uint_as_float(g_maxRb);
        float nh = sqrtf(sh2), nr = sqrtf(sr2);
        float E = (nh * Rbm + nr * Hbm + nr * Rbm) * 1.001f + 6e-3f;

        float e0 = g_h[a0] - d0;
        float e1 = g_h[a1] - d1;
        float e2 = g_h[a2] - d2;
        float e3 = g_h[a3] - d3;

        int w = a0; float ew = e0;
        if (betteri(e1, a1, ew, w)) { ew = e1; w = a1; }
        if (betteri(e2, a2, ew, w)) { ew = e2; w = a2; }
        if (betteri(e3, a3, ew, w)) { ew = e3; w = a3; }

        if (ew - bm > E) {
            g_idx[n] = w;
        } else {
            g_idx[n] = -1;
            g_bestu64[n] = 0ull;
            int p = atomicAdd(&g_fcount, 1);
            g_flist[p] = n;
        }
    }
}

// ---------------------------------------------------------------------------
// fallback2: 3-product MMA rescan of flagged samples (gathered A tiles).
// Persistent GRID CTAs over ceil(fcount/128) x 79 units. atomicMax publish.
// ---------------------------------------------------------------------------
__global__ void __launch_bounds__(256, 1)
fallback2_kernel(const float* __restrict__ x) {
    extern __shared__ __align__(1024) char smem[];
    const uint32_t sb = smem_u32(smem);
    const int tid = threadIdx.x;
    const int wid = tid >> 5;
    const int lane = tid & 31;
    const int l8 = lane & 7;
    const int gg = lane >> 3;
    const int mwarp = wid >> 2;
    const int nwarp = wid & 3;

    const int fcount = g_fcount;
    if (fcount == 0) return;
    const int nG = (fcount + 127) >> 7;
    const int total = nG * NT2;

    int* sids = reinterpret_cast<int*>(smem + F2_OFF_S);

    const uint32_t AQ  = sb + F2_OFF_A + (uint32_t)mwarp * 16384u
                       + (uint32_t)l8 * 272 + ((uint32_t)(gg & 1) << 11);
    const uint32_t gxa = (uint32_t)(gg >> 1) << 4;
    const uint32_t gxb = (uint32_t)(gg & 1) << 4;
    const uint32_t BQg = sb + F2_OFF_B + (uint32_t)nwarp * 8192u
                       + ((uint32_t)(gg >> 1) << 11) + (uint32_t)l8 * 272;

    for (int u = blockIdx.x; u < total; u += GRID) {
        const int gi = u / NT2;
        const int kt = u - gi * NT2;
        __syncthreads();

        if (tid < 128) {
            int fi = gi * 128 + tid;
            sids[tid] = (fi < fcount) ? g_flist[fi] : -1;
        }
        {
            const uint4* src = g_B4 + (size_t)kt * 4096;
#pragma unroll
            for (int i = 0; i < 16; i++)
                cp16(sb + F2_OFF_B + (uint32_t)(tid + i * 256) * 16,
                     src + tid + i * 256);
            if (tid < 32)
                cp16(sb + F2_OFF_H + (uint32_t)tid * 16,
                     (const char*)g_h + (size_t)kt * 512 + (size_t)tid * 16);
            CP_COMMIT();
        }
        __syncthreads();

        {
            const int row = tid >> 1;
            const int c0 = (tid & 1) * 8;
            const int n = sids[row];
            uint4* As = reinterpret_cast<uint4*>(smem + F2_OFF_A);
            if (n >= 0) {
                const float4* xr =
                    reinterpret_cast<const float4*>(x + (size_t)n * DD);
#pragma unroll
                for (int c = 0; c < 8; c++) {
                    float4 p = xr[(c0 + c) * 2];
                    float4 q = xr[(c0 + c) * 2 + 1];
                    float v[8] = {p.x, p.y, p.z, p.w, q.x, q.y, q.z, q.w};
                    uint4 H, M;
                    uint32_t* hp = &H.x; uint32_t* mp = &M.x;
#pragma unroll
                    for (int j = 0; j < 4; j++) {
                        float v0 = v[2 * j], v1 = v[2 * j + 1];
                        __half h0 = __float2half_rn(v0);
                        __half h1 = __float2half_rn(v1);
                        float r0 = v0 - __half2float(h0);
                        float r1 = v1 - __half2float(h1);
                        hp[j] = pk2h(v0, v1);
                        mp[j] = pk2h(r0, r1);
                    }
                    int ci = row * 16 + ((c0 + c) ^ (row & 7));
                    As[ci] = H;
                    As[ci + 2048] = M;
                }
            } else {
                uint4 Z = make_uint4(0, 0, 0, 0);
#pragma unroll
                for (int c = 0; c < 8; c++) {
                    int ci = row * 16 + ((c0 + c) ^ (row & 7));
                    As[ci] = Z;
                    As[ci + 2048] = Z;
                }
            }
        }
        asm volatile("cp.async.wait_group 0;" ::: "memory");
        __syncthreads();

        float acc[4][4][4];
#pragma unroll
        for (int ma = 0; ma < 4; ma++)
#pragma unroll
            for (int nn = 0; nn < 4; nn++)
#pragma unroll
                for (int r = 0; r < 4; r++) acc[ma][nn][r] = 0.f;

#pragma unroll
        for (int ks = 0; ks < 8; ks++) {
            const uint32_t kxa = ((uint32_t)ks << 5) | gxa;
            const uint32_t kxb = ((uint32_t)ks << 5) | gxb;
            uint32_t a[2][4][4];
            uint32_t bf[2][2][4];
#pragma unroll
            for (int s = 0; s < 2; s++)
#pragma unroll
                for (int ma = 0; ma < 4; ma++)
                    LDSM4(a[s][ma],
                          (AQ + (uint32_t)s * 32768 + (uint32_t)ma * 4096) ^ kxa);
#pragma unroll
            for (int s = 0; s < 2; s++)
#pragma unroll
                for (int nb = 0; nb < 2; nb++)
                    LDSM4(bf[s][nb],
                          (BQg + (uint32_t)s * 32768 + (uint32_t)nb * 4096) ^ kxb);

            const int PA[3] = {0, 0, 1};
            const int PB[3] = {0, 1, 0};
#pragma unroll
            for (int p = 0; p < 3; p++)
#pragma unroll
                for (int ma = 0; ma < 4; ma++)
#pragma unroll
                    for (int nn = 0; nn < 4; nn++)
                        MMA(acc[ma][nn], a[PA[p]][ma],
                            bf[PB[p]][nn >> 1][2 * (nn & 1)],
                            bf[PB[p]][nn >> 1][2 * (nn & 1) + 1]);
        }

        const float* hb = reinterpret_cast<const float*>(smem + F2_OFF_H);
        float* sbv = reinterpret_cast<float*>(smem + F2_OFF_A);
        int*   siv = reinterpret_cast<int*>(smem + F2_OFF_A + 2048);
        __syncthreads();
#pragma unroll
        for (int ma = 0; ma < 4; ma++)
#pragma unroll
            for (int rh = 0; rh < 2; rh++) {
                float bv = -3.4e38f;
                int bix = 0;
#pragma unroll
                for (int nn = 0; nn < 4; nn++) {
                    int hi0 = nwarp * 32 + nn * 8 + (lane & 3) * 2;
                    float d0 = hb[hi0] - acc[ma][nn][2 * rh];
                    float d1 = hb[hi0 + 1] - acc[ma][nn][2 * rh + 1];
                    int k0 = kt * KT + hi0;
                    if (d0 > bv) { bv = d0; bix = k0; }
                    if (d1 > bv) { bv = d1; bix = k0 + 1; }
                }
#pragma unroll
                for (int off = 1; off < 4; off <<= 1) {
                    float ov = __shfl_xor_sync(0xffffffffu, bv, off);
                    int   oi = __shfl_xor_sync(0xffffffffu, bix, off);
                    if (ov > bv || (ov == bv && oi < bix)) { bv = ov; bix = oi; }
                }
                if ((lane & 3) == 0) {
                    int row = mwarp * 64 + ma * 16 + rh * 8 + (lane >> 2);
                    sbv[row * 4 + nwarp] = bv;
                    siv[row * 4 + nwarp] = bix;
                }
            }
        __syncthreads();
        if (tid < 128) {
            float bv = sbv[tid * 4];
            int bix = siv[tid * 4];
#pragma unroll
            for (int w = 1; w < 4; w++) {
                float v = sbv[tid * 4 + w];
                int ix = siv[tid * 4 + w];
                if (v > bv || (v == bv && ix < bix)) { bv = v; bix = ix; }
            }
            int sid = sids[tid];
            if (sid >= 0) {
                unsigned long long key =
                    ((unsigned long long)enc_f(bv) << 32)
                    | (unsigned long long)(0xFFFFFFFFu - (unsigned)bix);
                atomicMax(&g_bestu64[sid], key);
            }
        }
    }
}

// ---------------------------------------------------------------------------
// gather quantize + index output + MSE (last block folds final reduction)
// ---------------------------------------------------------------------------
__global__ void gather_kernel(const float* __restrict__ x,
                              float* __restrict__ out) {
    __shared__ float red[256];
    __shared__ bool last;
    const int tid = threadIdx.x;
    float* out_q = out;
    float* out_idx_f = out + (size_t)NS * DD;

    int gt = blockIdx.x * 256 + tid;
    if (gt < NS) {
        int ix = g_idx[gt];
        if (ix < 0)
            ix = (int)(0xFFFFFFFFu - (unsigned)(g_bestu64[gt] & 0xFFFFFFFFull));
        out_idx_f[gt] = (float)ix;
    }

    float local = 0.f;
    for (int e4 = blockIdx.x * 256 + tid; e4 < NS * DD / 4;
         e4 += gridDim.x * 256) {
        int n = e4 >> 5;
        int d4 = (e4 & 31) * 4;
        int ix = g_idx[n];
        if (ix < 0)
            ix = (int)(0xFFFFFFFFu - (unsigned)(g_bestu64[n] & 0xFFFFFFFFull));
        float4 q = *reinterpret_cast<const float4*>(g_cmT + (size_t)ix * DD + d4);
        float4 xv = reinterpret_cast<const float4*>(x)[e4];
        reinterpret_cast<float4*>(out_q)[e4] = q;
        float a = xv.x - q.x, b = xv.y - q.y, c = xv.z - q.z, d = xv.w - q.w;
        local = fmaf(a, a, local);
        local = fmaf(b, b, local);
        local = fmaf(c, c, local);
        local = fmaf(d, d, local);
    }
    red[tid] = local;
    __syncthreads();
    for (int s = 128; s; s >>= 1) {
        if (tid < s) red[tid] += red[tid + s];
        __syncthreads();
    }
    if (tid == 0) {
        g_partial[blockIdx.x] = red[0];
        __threadfence();
        unsigned t = atomicAdd(&g_done, 1u);
        last = (t == gridDim.x - 1);
    }
    __syncthreads();
    if (last) {
        __threadfence();
        volatile float* gp = g_partial;
        __shared__ double dred[256];
        double acc = 0.0;
        for (int i = tid; i < 1024; i += 256) acc += (double)gp[i];
        dred[tid] = acc;
        __syncthreads();
        for (int st = 128; st; st >>= 1) {
            if (tid < st) dred[tid] += dred[tid + st];
            __syncthreads();
        }
        if (tid == 0)
            out[(size_t)NS * DD + NS] =
                (float)(dred[0] / (double)((size_t)NS * DD));
    }
}

// ---------------------------------------------------------------------------
extern "C" void kernel_launch(void* const* d_in, const int* in_sizes, int n_in,
                              void* d_out, int out_size) {
    const float* x  = (const float*)d_in[0];   // [16384, 128]
    const float* cm = (const float*)d_in[1];   // [128, 10000]
    float* out = (float*)d_out;                // [quantize | index | diff]

    cudaFuncSetAttribute(vq_main,
                         cudaFuncAttributeMaxDynamicSharedMemorySize, SMEM_TOTAL);
    cudaFuncSetAttribute(fallback2_kernel,
                         cudaFuncAttributeMaxDynamicSharedMemorySize, F2_SMEM);

    prepB_kernel<<<NT2 * 4, 256>>>(cm);
    vq_main<<<GRID2, 256, SMEM_TOTAL>>>(x);
    decision_kernel<<<NS / 8, 256>>>(x);
    fallback2_kernel<<<GRID, 256, F2_SMEM>>>(x);
    gather_kernel<<<1024, 256>>>(x, out);
}